// round 3
// baseline (speedup 1.0000x reference)
#include <cuda_runtime.h>
#include <cstdint>

// ============================================================================
// Problem dims
// ============================================================================
constexpr int MTOT = 8192;          // B*S
constexpr int KTOT = 4096;          // H
constexpr int NQ   = 4096;
constexpr int NKV  = 1024;
constexpr int NTOT = NQ + 2 * NKV;  // 6144
constexpr float SCALING = 2.0f;

// GEMM tiling (mma.sync tf32 path — compute_100 target has no tcgen05)
constexpr int BM = 128, BN = 128, BK = 32, STAGES = 3;
constexpr int KBLKS = KTOT / BK;    // 128
constexpr int NBLKS = NTOT / BN;    // 48
constexpr int MBLKS = MTOT / BM;    // 64
constexpr int TILE_F = BM * BK;     // 4096 floats (16 KB) per A or B stage
constexpr int SMEM_TOTAL = STAGES * 2 * TILE_F * 4;  // 98304 bytes

// ============================================================================
// Scratch (device globals — no allocation allowed)
// ============================================================================
__device__ float g_xt[(size_t)MTOT * KTOT];   // x, tf32(RNA)-rounded, row-major [M][K]
__device__ float g_wc[(size_t)NTOT * KTOT];   // W + SCALING*(A@B)^T, tf32(RNA), row-major [N][K]
__device__ float g_bias[NTOT];

// ============================================================================
// Helpers
// ============================================================================
__device__ __forceinline__ uint32_t smem_u32(const void* p) {
    uint32_t a;
    asm("{ .reg .u64 t; cvta.to.shared.u64 t, %1; cvt.u32.u64 %0, t; }" : "=r"(a) : "l"(p));
    return a;
}

#define CP_ASYNC16(dst, src) \
    asm volatile("cp.async.cg.shared.global [%0], [%1], 16;" :: "r"(dst), "l"(src) : "memory")
#define CP_COMMIT() asm volatile("cp.async.commit_group;" ::: "memory")
#define CP_WAIT(n)  asm volatile("cp.async.wait_group %0;" :: "n"(n) : "memory")

__device__ __forceinline__ float tf32_rna(float v) {
    uint32_t t;
    asm("cvt.rna.tf32.f32 %0, %1;" : "=r"(t) : "f"(v));
    return __uint_as_float(t);
}

// element offset (in floats) of (row, col) in a 128x32 tile with float4 XOR swizzle
__device__ __forceinline__ int sw_off(int row, int col) {
    return (row << 5) + ((((col >> 2) ^ (row & 7)) << 2) | (col & 3));
}

__device__ __forceinline__ void mma_tf32(float* c, const float* a, const float* b) {
    asm volatile(
        "mma.sync.aligned.m16n8k8.row.col.f32.tf32.tf32.f32 "
        "{%0,%1,%2,%3}, {%4,%5,%6,%7}, {%8,%9}, {%0,%1,%2,%3};"
        : "+f"(c[0]), "+f"(c[1]), "+f"(c[2]), "+f"(c[3])
        : "r"(__float_as_uint(a[0])), "r"(__float_as_uint(a[1])),
          "r"(__float_as_uint(a[2])), "r"(__float_as_uint(a[3])),
          "r"(__float_as_uint(b[0])), "r"(__float_as_uint(b[1])));
}

// ============================================================================
// Pre-pass 1: x -> tf32(RNA), row-major copy (vectorized)
// ============================================================================
__global__ __launch_bounds__(256) void prep_x(const float* __restrict__ x) {
    size_t i = ((size_t)blockIdx.x * 256 + threadIdx.x) * 4;
    float4 v = *reinterpret_cast<const float4*>(x + i);
    v.x = tf32_rna(v.x); v.y = tf32_rna(v.y); v.z = tf32_rna(v.z); v.w = tf32_rna(v.w);
    *reinterpret_cast<float4*>(g_xt + i) = v;
}

// ============================================================================
// Pre-pass 2: Wc[n][h] = W[n][h] + SCALING * sum_r A[h][r]*B[r][n]   -> tf32(RNA)
// Each block: 16 n-values x 256 h-values. B segment staged in smem.
// ============================================================================
__global__ __launch_bounds__(256) void prep_w(
    const float* __restrict__ Wq, const float* __restrict__ Wk, const float* __restrict__ Wv,
    const float* __restrict__ Aq, const float* __restrict__ Bq,
    const float* __restrict__ Ak, const float* __restrict__ Bk,
    const float* __restrict__ Av, const float* __restrict__ Bv) {
    __shared__ float sB[16][16];   // [r][j]  B[r][n0+j]
    const int h  = blockIdx.x * 256 + threadIdx.x;
    const int n0 = blockIdx.y * 16;

    const float *W, *A, *Bm;
    int nn0, od;
    if (n0 < NQ)            { W = Wq; A = Aq; Bm = Bq; nn0 = n0;             od = NQ;  }
    else if (n0 < NQ + NKV) { W = Wk; A = Ak; Bm = Bk; nn0 = n0 - NQ;        od = NKV; }
    else                    { W = Wv; A = Av; Bm = Bv; nn0 = n0 - NQ - NKV;  od = NKV; }

    if (threadIdx.x < 256) {
        int r = threadIdx.x >> 4, j = threadIdx.x & 15;
        if (threadIdx.x < 256) sB[r][j] = Bm[r * od + nn0 + j];
    }
    __syncthreads();

    // A row for this h: 16 contiguous floats
    float a[16];
    const float4* ap = reinterpret_cast<const float4*>(A + (size_t)h * 16);
    #pragma unroll
    for (int q = 0; q < 4; q++) {
        float4 v = ap[q];
        a[q * 4 + 0] = v.x; a[q * 4 + 1] = v.y; a[q * 4 + 2] = v.z; a[q * 4 + 3] = v.w;
    }

    #pragma unroll
    for (int j = 0; j < 16; j++) {
        float acc = W[(size_t)(nn0 + j) * KTOT + h];
        #pragma unroll
        for (int r = 0; r < 16; r++)
            acc += SCALING * a[r] * sB[r][j];
        g_wc[(size_t)(n0 + j) * KTOT + h] = tf32_rna(acc);
    }
}

__global__ __launch_bounds__(256) void prep_bias(const float* __restrict__ bq,
                                                 const float* __restrict__ bk,
                                                 const float* __restrict__ bv) {
    int n = blockIdx.x * 256 + threadIdx.x;
    if (n >= NTOT) return;
    g_bias[n] = (n < NQ) ? bq[n] : (n < NQ + NKV ? bk[n - NQ] : bv[n - NQ - NKV]);
}

// ============================================================================
// Main GEMM: 128x128x32 CTA tile, 8 warps (64x32 warp tiles), 3-stage cp.async,
// mma.sync.m16n8k8.tf32
// ============================================================================
__global__ __launch_bounds__(256, 2) void gemm_kernel(float* __restrict__ out) {
    extern __shared__ float smem[];   // [STAGES][2][4096]: A then B per stage
    const int tid = threadIdx.x, wid = tid >> 5, lane = tid & 31;
    const int gid = lane >> 2, tig = lane & 3;     // mma group / thread-in-group
    const int warp_m = wid & 1, warp_n = wid >> 1; // 2 x 4 warp grid

    // GROUP_M=16 rasterization: per-wave working set ~68 MB (fits L2)
    constexpr int GROUP_M = 16;
    constexpr int GS = GROUP_M * NBLKS;
    int gi = blockIdx.x / GS, rem = blockIdx.x - gi * GS;
    int pm = gi * GROUP_M + (rem % GROUP_M);
    int pn = rem / GROUP_M;

    const float* abase = g_xt + (size_t)pm * BM * KTOT;
    const float* bbase = g_wc + (size_t)pn * BN * KTOT;
    uint32_t sb = smem_u32(smem);

    // per-thread cp.async pattern: 4 float4 per matrix per stage
    // idx = tid + i*256 in [0,1024): row = idx>>3, c4 = idx&7
    auto load_stage = [&](int kb, int st) {
        const float* as = abase + kb * BK;
        const float* bs = bbase + kb * BK;
        uint32_t dA = sb + (uint32_t)(st * 2 * TILE_F) * 4;
        uint32_t dB = dA + TILE_F * 4;
        #pragma unroll
        for (int i = 0; i < 4; i++) {
            int idx = tid + i * 256;
            int row = idx >> 3, c4 = idx & 7;
            int doff = ((row << 5) + ((c4 ^ (row & 7)) << 2)) * 4;
            CP_ASYNC16(dA + doff, as + (size_t)row * KTOT + c4 * 4);
            CP_ASYNC16(dB + doff, bs + (size_t)row * KTOT + c4 * 4);
        }
        CP_COMMIT();
    };

    // prologue: stages 0..STAGES-2
    #pragma unroll
    for (int s = 0; s < STAGES - 1; s++) load_stage(s, s);

    float acc[4][4][4];
    #pragma unroll
    for (int i = 0; i < 4; i++)
        #pragma unroll
        for (int j = 0; j < 4; j++)
            #pragma unroll
            for (int k = 0; k < 4; k++) acc[i][j][k] = 0.0f;

    int st = 0;
    for (int kb = 0; kb < KBLKS; kb++) {
        CP_WAIT(STAGES - 2);
        __syncthreads();

        // issue next stage load (slot being overwritten was computed last iter;
        // the barrier above makes that safe)
        int nkb = kb + STAGES - 1;
        if (nkb < KBLKS) load_stage(nkb, (st + STAGES - 1) % STAGES);
        else CP_COMMIT();

        const float* sA = smem + st * 2 * TILE_F;
        const float* sB_ = sA + TILE_F;

        #pragma unroll
        for (int ks = 0; ks < 4; ks++) {
            const int k0 = ks * 8;
            float a[4][4], b[4][2];
            #pragma unroll
            for (int mf = 0; mf < 4; mf++) {
                int r = warp_m * 64 + mf * 16 + gid;
                a[mf][0] = sA[sw_off(r,     k0 + tig)];
                a[mf][1] = sA[sw_off(r + 8, k0 + tig)];
                a[mf][2] = sA[sw_off(r,     k0 + tig + 4)];
                a[mf][3] = sA[sw_off(r + 8, k0 + tig + 4)];
            }
            #pragma unroll
            for (int nf = 0; nf < 4; nf++) {
                int n = warp_n * 32 + nf * 8 + gid;
                b[nf][0] = sB_[sw_off(n, k0 + tig)];
                b[nf][1] = sB_[sw_off(n, k0 + tig + 4)];
            }
            #pragma unroll
            for (int mf = 0; mf < 4; mf++)
                #pragma unroll
                for (int nf = 0; nf < 4; nf++)
                    mma_tf32(acc[mf][nf], a[mf], b[nf]);
        }
        st = (st + 1) % STAGES;
        __syncthreads();   // compute done before this slot is refilled next iters
    }

    // ---- epilogue: bias + store ----
    const int n_tile0 = pn * BN;
    float* obase;
    int ncols;
    if (n_tile0 < NQ)            { obase = out;                                      ncols = NQ;  }
    else if (n_tile0 < NQ + NKV) { obase = out + (size_t)MTOT * NQ;                  ncols = NKV; }
    else                         { obase = out + (size_t)MTOT * (NQ + NKV);          ncols = NKV; }
    int nseg0 = (n_tile0 < NQ) ? n_tile0 : (n_tile0 < NQ + NKV ? n_tile0 - NQ : n_tile0 - NQ - NKV);

    #pragma unroll
    for (int mf = 0; mf < 4; mf++) {
        int m0 = pm * BM + warp_m * 64 + mf * 16 + gid;
        #pragma unroll
        for (int nf = 0; nf < 4; nf++) {
            int nc = warp_n * 32 + nf * 8 + tig * 2;          // within tile
            int ng = n_tile0 + nc;                            // global fused col
            float b0 = g_bias[ng], b1 = g_bias[ng + 1];
            float2 v0 = make_float2(acc[mf][nf][0] + b0, acc[mf][nf][1] + b1);
            float2 v1 = make_float2(acc[mf][nf][2] + b0, acc[mf][nf][3] + b1);
            *reinterpret_cast<float2*>(obase + (size_t)m0 * ncols + nseg0 + nc)       = v0;
            *reinterpret_cast<float2*>(obase + (size_t)(m0 + 8) * ncols + nseg0 + nc) = v1;
        }
    }
}

// ============================================================================
// kernel_launch
// ============================================================================
extern "C" void kernel_launch(void* const* d_in, const int* in_sizes, int n_in,
                              void* d_out, int out_size) {
    const float* x  = (const float*)d_in[0];
    const float* Wq = (const float*)d_in[1];
    const float* Wk = (const float*)d_in[2];
    const float* Wv = (const float*)d_in[3];
    const float* bq = (const float*)d_in[4];
    const float* bk = (const float*)d_in[5];
    const float* bv = (const float*)d_in[6];
    const float* Aq = (const float*)d_in[7];
    const float* Bq = (const float*)d_in[8];
    const float* Ak = (const float*)d_in[9];
    const float* Bk = (const float*)d_in[10];
    const float* Av = (const float*)d_in[11];
    const float* Bv = (const float*)d_in[12];
    float* out = (float*)d_out;

    cudaFuncSetAttribute(gemm_kernel, cudaFuncAttributeMaxDynamicSharedMemorySize, SMEM_TOTAL);

    prep_x<<<(int)(((size_t)MTOT * KTOT / 4) / 256), 256>>>(x);
    {
        dim3 g(KTOT / 256, NTOT / 16);
        prep_w<<<g, 256>>>(Wq, Wk, Wv, Aq, Bq, Ak, Bk, Av, Bv);
    }
    prep_bias<<<(NTOT + 255) / 256, 256>>>(bq, bk, bv);
    gemm_kernel<<<MBLKS * NBLKS, 256, SMEM_TOTAL>>>(out);
}

// round 5
// speedup vs baseline: 2.4470x; 2.4470x over previous
#include <cuda_runtime.h>
#include <cstdint>

// ============================================================================
// Problem dims
// ============================================================================
constexpr int MTOT = 8192;          // B*S
constexpr int KTOT = 4096;          // H
constexpr int NQ   = 4096;
constexpr int NKV  = 1024;
constexpr int NTOT = NQ + 2 * NKV;  // 6144
constexpr float SCALING = 2.0f;

// GEMM tiling
constexpr int BM = 128, BN = 128, BK = 32, STAGES = 3;
constexpr int KBLKS = KTOT / BK;    // 128
constexpr int NBLKS = NTOT / BN;    // 48
constexpr int MBLKS = MTOT / BM;    // 64
constexpr int TILE_F = BM * BK;     // 4096 floats (16 KB) per A or B tile
constexpr int SMEM_TOTAL = STAGES * 2 * TILE_F * 4;  // 98304 bytes

// ============================================================================
// Scratch (device globals)
// g_xt: [MBLKS][KBLKS] tiles, each tile fragment-packed:
//       [warp_m(2)][mf(4)][ks(4)][lane(32)] float4  (A operands of one mma)
// g_wc: [NBLKS][KBLKS] tiles, fragment-packed:
//       [warp_n(4)][pair(2)][ks(4)][lane(32)] float4 (B operands of two n-frags)
// ============================================================================
__device__ float g_xt[(size_t)MTOT * KTOT];
__device__ float g_wc[(size_t)NTOT * KTOT];
__device__ float g_bias[NTOT];

// ============================================================================
// Helpers
// ============================================================================
__device__ __forceinline__ uint32_t smem_u32(const void* p) {
    uint32_t a;
    asm("{ .reg .u64 t; cvta.to.shared.u64 t, %1; cvt.u32.u64 %0, t; }" : "=r"(a) : "l"(p));
    return a;
}

#define CP_ASYNC16(dst, src) \
    asm volatile("cp.async.cg.shared.global [%0], [%1], 16;" :: "r"(dst), "l"(src) : "memory")
#define CP_COMMIT() asm volatile("cp.async.commit_group;" ::: "memory")
#define CP_WAIT(n)  asm volatile("cp.async.wait_group %0;" :: "n"(n) : "memory")

__device__ __forceinline__ float tf32_rna(float v) {
    uint32_t t;
    asm("cvt.rna.tf32.f32 %0, %1;" : "=r"(t) : "f"(v));
    return __uint_as_float(t);
}

__device__ __forceinline__ void mma_tf32(float* c, const float4& a, const float* b) {
    asm volatile(
        "mma.sync.aligned.m16n8k8.row.col.f32.tf32.tf32.f32 "
        "{%0,%1,%2,%3}, {%4,%5,%6,%7}, {%8,%9}, {%0,%1,%2,%3};"
        : "+f"(c[0]), "+f"(c[1]), "+f"(c[2]), "+f"(c[3])
        : "r"(__float_as_uint(a.x)), "r"(__float_as_uint(a.y)),
          "r"(__float_as_uint(a.z)), "r"(__float_as_uint(a.w)),
          "r"(__float_as_uint(b[0])), "r"(__float_as_uint(b[1])));
}

// ============================================================================
// Pre-pass 1: x -> tf32(RNA), fragment-packed tiles.
// Element (m, k):  mb=m>>7, mr=m&127; warp_m=mr>>6, mf=(mr>>4)&3, gid=mr&7,
//                  half=(mr>>3)&1; kb=k>>5, kc=k&31, ks=kc>>3, tig=kc&3,
//                  khalf=(kc>>2)&1; lane=gid*4+tig; e = half + 2*khalf
// ============================================================================
__global__ __launch_bounds__(256) void prep_x(const float* __restrict__ x) {
    size_t f = (size_t)blockIdx.x * 256 + threadIdx.x;     // float4 index
    int m = (int)(f >> 10);                                // KTOT/4 = 1024 float4/row
    int k = ((int)(f & 1023)) << 2;                        // k of .x; tig = j
    float4 v = *reinterpret_cast<const float4*>(x + f * 4);

    int mb = m >> 7, mr = m & 127;
    int warp_m = mr >> 6, mf = (mr >> 4) & 3, gid = mr & 7, half = (mr >> 3) & 1;
    int kb = k >> 5, kc = k & 31, ks = kc >> 3, khalf = (kc >> 2) & 1;
    int e = half + 2 * khalf;
    float* tile = g_xt + (size_t)(mb * KBLKS + kb) * TILE_F;
    int base = (((warp_m * 4 + mf) * 4 + ks) * 32 + gid * 4) * 4 + e;
    tile[base +  0] = tf32_rna(v.x);   // tig=0
    tile[base +  4] = tf32_rna(v.y);   // tig=1 -> lane+1 -> +4 floats
    tile[base +  8] = tf32_rna(v.z);
    tile[base + 12] = tf32_rna(v.w);
}

// ============================================================================
// Pre-pass 2: Wc[n][h] = W[n][h] + SCALING * sum_r A[h][r]*B[r][n] -> tf32(RNA),
// fragment-packed. Element (n, k=h): nb=n>>7, nr=n&127; warp_n=nr>>5,
// pair=(nr>>4)&1, gid=nr&7, half=(nr>>3)&1; e = khalf + 2*half
// ============================================================================
__global__ __launch_bounds__(256) void prep_w(
    const float* __restrict__ Wq, const float* __restrict__ Wk, const float* __restrict__ Wv,
    const float* __restrict__ Aq, const float* __restrict__ Bq,
    const float* __restrict__ Ak, const float* __restrict__ Bk,
    const float* __restrict__ Av, const float* __restrict__ Bv) {
    __shared__ float sB[16][16];   // [r][j] = B[r][n0+j]
    const int h  = blockIdx.x * 256 + threadIdx.x;
    const int n0 = blockIdx.y * 16;

    const float *W, *A, *Bm;
    int nn0, od;
    if (n0 < NQ)            { W = Wq; A = Aq; Bm = Bq; nn0 = n0;             od = NQ;  }
    else if (n0 < NQ + NKV) { W = Wk; A = Ak; Bm = Bk; nn0 = n0 - NQ;        od = NKV; }
    else                    { W = Wv; A = Av; Bm = Bv; nn0 = n0 - NQ - NKV;  od = NKV; }

    {
        int r = threadIdx.x >> 4, j = threadIdx.x & 15;
        sB[r][j] = Bm[r * od + nn0 + j];
    }
    __syncthreads();

    float a[16];
    const float4* ap = reinterpret_cast<const float4*>(A + (size_t)h * 16);
    #pragma unroll
    for (int q = 0; q < 4; q++) {
        float4 v = ap[q];
        a[q * 4 + 0] = v.x; a[q * 4 + 1] = v.y; a[q * 4 + 2] = v.z; a[q * 4 + 3] = v.w;
    }

    // k-decomposition for this h (same for all 16 n)
    int kb = h >> 5, kc = h & 31, ks = kc >> 3, tig = kc & 3, khalf = (kc >> 2) & 1;

    #pragma unroll
    for (int j = 0; j < 16; j++) {
        float acc = W[(size_t)(nn0 + j) * KTOT + h];
        #pragma unroll
        for (int r = 0; r < 16; r++)
            acc += SCALING * a[r] * sB[r][j];
        int n = n0 + j;
        int nb = n >> 7, nr = n & 127;
        int warp_n = nr >> 5, pair = (nr >> 4) & 1, gid = nr & 7, half = (nr >> 3) & 1;
        float* tile = g_wc + (size_t)(nb * KBLKS + kb) * TILE_F;
        int off = (((warp_n * 2 + pair) * 4 + ks) * 32 + gid * 4 + tig) * 4 + khalf + 2 * half;
        tile[off] = tf32_rna(acc);
    }
}

__global__ __launch_bounds__(256) void prep_bias(const float* __restrict__ bq,
                                                 const float* __restrict__ bk,
                                                 const float* __restrict__ bv) {
    int n = blockIdx.x * 256 + threadIdx.x;
    if (n >= NTOT) return;
    g_bias[n] = (n < NQ) ? bq[n] : (n < NQ + NKV ? bk[n - NQ] : bv[n - NQ - NKV]);
}

// ============================================================================
// Main GEMM: 128x128x32 CTA, 8 warps (64x32 warp tiles), 3-stage cp.async,
// fragment-packed smem -> pure LDS.128 fragment loads, mma.sync tf32.
// ============================================================================
__global__ __launch_bounds__(256, 2) void gemm_kernel(float* __restrict__ out) {
    extern __shared__ float smem[];   // [STAGES][2][TILE_F]: A then B per stage
    const int tid = threadIdx.x, wid = tid >> 5, lane = tid & 31;
    const int gid = lane >> 2, tig = lane & 3;
    const int warp_m = wid & 1, warp_n = wid >> 1;

    constexpr int GROUP_M = 16;
    constexpr int GS = GROUP_M * NBLKS;
    int gi = blockIdx.x / GS, rem = blockIdx.x - gi * GS;
    int pm = gi * GROUP_M + (rem % GROUP_M);
    int pn = rem / GROUP_M;

    const float* abase = g_xt + (size_t)pm * KBLKS * TILE_F;
    const float* bbase = g_wc + (size_t)pn * KBLKS * TILE_F;
    uint32_t sb = smem_u32(smem);

    // contiguous tile copy: 1024 float4 per tile, 4 per thread per matrix
    auto load_stage = [&](int kb, int st) {
        const float* as = abase + (size_t)kb * TILE_F;
        const float* bs = bbase + (size_t)kb * TILE_F;
        uint32_t dA = sb + (uint32_t)(st * 2 * TILE_F) * 4;
        uint32_t dB = dA + TILE_F * 4;
        #pragma unroll
        for (int i = 0; i < 4; i++) {
            int idx = (tid + i * 256) * 4;           // float offset
            CP_ASYNC16(dA + idx * 4, as + idx);
            CP_ASYNC16(dB + idx * 4, bs + idx);
        }
        CP_COMMIT();
    };

    #pragma unroll
    for (int s = 0; s < STAGES - 1; s++) load_stage(s, s);

    float acc[4][4][4];
    #pragma unroll
    for (int i = 0; i < 4; i++)
        #pragma unroll
        for (int j = 0; j < 4; j++)
            #pragma unroll
            for (int k = 0; k < 4; k++) acc[i][j][k] = 0.0f;

    // per-warp fragment base offsets (floats)
    // A frag addr: ((warp_m*16 + mf*4 + ks)*32 + lane) * 4
    // B frag addr: TILE_F + ((warp_n*8 + pair*4 + ks)*32 + lane) * 4
    const int aoff0 = (warp_m * 16 * 32 + lane) * 4;
    const int boff0 = TILE_F + (warp_n * 8 * 32 + lane) * 4;

    int st = 0;
    for (int kb = 0; kb < KBLKS; kb++) {
        CP_WAIT(STAGES - 2);
        __syncthreads();

        int nkb = kb + STAGES - 1;
        if (nkb < KBLKS) load_stage(nkb, (st + STAGES - 1) % STAGES);
        else CP_COMMIT();

        const float* sbase = smem + st * 2 * TILE_F;

        #pragma unroll
        for (int ks = 0; ks < 4; ks++) {
            float4 a[4];
            float  b[4][2];
            #pragma unroll
            for (int mf = 0; mf < 4; mf++)
                a[mf] = *reinterpret_cast<const float4*>(sbase + aoff0 + (mf * 4 + ks) * 128);
            #pragma unroll
            for (int p = 0; p < 2; p++) {
                float4 q = *reinterpret_cast<const float4*>(sbase + boff0 + (p * 4 + ks) * 128);
                b[2 * p + 0][0] = q.x; b[2 * p + 0][1] = q.y;
                b[2 * p + 1][0] = q.z; b[2 * p + 1][1] = q.w;
            }
            #pragma unroll
            for (int mf = 0; mf < 4; mf++)
                #pragma unroll
                for (int nf = 0; nf < 4; nf++)
                    mma_tf32(acc[mf][nf], a[mf], b[nf]);
        }
        st = (st + 1) % STAGES;
        __syncthreads();
    }

    // ---- epilogue: bias + store ----
    const int n_tile0 = pn * BN;
    float* obase;
    int ncols;
    if (n_tile0 < NQ)            { obase = out;                             ncols = NQ;  }
    else if (n_tile0 < NQ + NKV) { obase = out + (size_t)MTOT * NQ;         ncols = NKV; }
    else                         { obase = out + (size_t)MTOT * (NQ + NKV); ncols = NKV; }
    int nseg0 = (n_tile0 < NQ) ? n_tile0 : (n_tile0 < NQ + NKV ? n_tile0 - NQ : n_tile0 - NQ - NKV);

    #pragma unroll
    for (int mf = 0; mf < 4; mf++) {
        int m0 = pm * BM + warp_m * 64 + mf * 16 + gid;
        #pragma unroll
        for (int nf = 0; nf < 4; nf++) {
            int nc = warp_n * 32 + nf * 8 + tig * 2;
            int ng = n_tile0 + nc;
            float b0 = g_bias[ng], b1 = g_bias[ng + 1];
            float2 v0 = make_float2(acc[mf][nf][0] + b0, acc[mf][nf][1] + b1);
            float2 v1 = make_float2(acc[mf][nf][2] + b0, acc[mf][nf][3] + b1);
            *reinterpret_cast<float2*>(obase + (size_t)m0 * ncols + nseg0 + nc)       = v0;
            *reinterpret_cast<float2*>(obase + (size_t)(m0 + 8) * ncols + nseg0 + nc) = v1;
        }
    }
}

// ============================================================================
// kernel_launch
// ============================================================================
extern "C" void kernel_launch(void* const* d_in, const int* in_sizes, int n_in,
                              void* d_out, int out_size) {
    const float* x  = (const float*)d_in[0];
    const float* Wq = (const float*)d_in[1];
    const float* Wk = (const float*)d_in[2];
    const float* Wv = (const float*)d_in[3];
    const float* bq = (const float*)d_in[4];
    const float* bk = (const float*)d_in[5];
    const float* bv = (const float*)d_in[6];
    const float* Aq = (const float*)d_in[7];
    const float* Bq = (const float*)d_in[8];
    const float* Ak = (const float*)d_in[9];
    const float* Bk = (const float*)d_in[10];
    const float* Av = (const float*)d_in[11];
    const float* Bv = (const float*)d_in[12];
    float* out = (float*)d_out;

    cudaFuncSetAttribute(gemm_kernel, cudaFuncAttributeMaxDynamicSharedMemorySize, SMEM_TOTAL);

    prep_x<<<(int)(((size_t)MTOT * KTOT / 4) / 256), 256>>>(x);
    {
        dim3 g(KTOT / 256, NTOT / 16);
        prep_w<<<g, 256>>>(Wq, Wk, Wv, Aq, Bq, Ak, Bk, Av, Bv);
    }
    prep_bias<<<(NTOT + 255) / 256, 256>>>(bq, bk, bv);
    gemm_kernel<<<MBLKS * NBLKS, 256, SMEM_TOTAL>>>(out);
}

// round 6
// speedup vs baseline: 4.6248x; 1.8900x over previous
#include <cuda_runtime.h>
#include <cuda_fp16.h>
#include <cstdint>

// ============================================================================
// Problem dims
// ============================================================================
constexpr int MTOT = 8192;          // B*S
constexpr int KTOT = 4096;          // H
constexpr int NQ   = 4096;
constexpr int NKV  = 1024;
constexpr int NTOT = NQ + 2 * NKV;  // 6144
constexpr float SCALING = 2.0f;

// GEMM tiling (fp16 mma.sync m16n8k16)
constexpr int BM = 128, BN = 128, BK = 64, STAGES = 3;
constexpr int KBLKS = KTOT / BK;    // 64
constexpr int NBLKS = NTOT / BN;    // 48
constexpr int MBLKS = MTOT / BM;    // 64
constexpr int TILE_H = BM * BK;     // 8192 halves = 16 KB per A or B tile
constexpr int TILE_BYTES = TILE_H * 2;               // 16384
constexpr int SMEM_TOTAL = STAGES * 2 * TILE_BYTES;  // 98304

// ============================================================================
// Scratch (device globals)
// g_xt: [MBLKS][KBLKS] tiles, fragment-packed for m16n8k16 A:
//       [warp_m(2)][mf(4)][ks(4)][lane(32)][8 halves]
// g_wc: [NBLKS][KBLKS] tiles, fragment-packed for B (two n-frags per 16B):
//       [warp_n(4)][pair(2)][ks(4)][lane(32)][8 halves]
// ============================================================================
__device__ __half g_xt[(size_t)MTOT * KTOT];
__device__ __half g_wc[(size_t)NTOT * KTOT];
__device__ float  g_bias[NTOT];

// ============================================================================
// Helpers
// ============================================================================
__device__ __forceinline__ uint32_t smem_u32(const void* p) {
    uint32_t a;
    asm("{ .reg .u64 t; cvta.to.shared.u64 t, %1; cvt.u32.u64 %0, t; }" : "=r"(a) : "l"(p));
    return a;
}

#define CP_ASYNC16(dst, src) \
    asm volatile("cp.async.cg.shared.global [%0], [%1], 16;" :: "r"(dst), "l"(src) : "memory")
#define CP_COMMIT() asm volatile("cp.async.commit_group;" ::: "memory")
#define CP_WAIT(n)  asm volatile("cp.async.wait_group %0;" :: "n"(n) : "memory")

__device__ __forceinline__ void mma_f16(float* c, const uint4& a, uint32_t b0, uint32_t b1) {
    asm volatile(
        "mma.sync.aligned.m16n8k16.row.col.f32.f16.f16.f32 "
        "{%0,%1,%2,%3}, {%4,%5,%6,%7}, {%8,%9}, {%0,%1,%2,%3};"
        : "+f"(c[0]), "+f"(c[1]), "+f"(c[2]), "+f"(c[3])
        : "r"(a.x), "r"(a.y), "r"(a.z), "r"(a.w), "r"(b0), "r"(b1));
}

// ============================================================================
// Pre-pass 1: x -> fp16(RNE), fragment-packed A tiles.
// Element (m, k): mb=m>>7, mr=m&127 -> warp_m=mr>>6, mf=(mr>>4)&3,
//   half_m=(mr>>3)&1, gid=mr&7.  kb=k>>6, kc=k&63 -> ks=kc>>4, kk=kc&15,
//   tig=(kk>>1)&3, klo=kk&1, khi=kk>>3.  half-slot e = klo + 2*half_m + 4*khi.
// One thread handles 4 consecutive k (float4): two half2 stores (tig, tig+1).
// ============================================================================
__global__ __launch_bounds__(256) void prep_x(const float* __restrict__ x) {
    size_t f = (size_t)blockIdx.x * 256 + threadIdx.x;     // float4 index
    int m = (int)(f >> 10);                                // KTOT/4 = 1024 per row
    int k = ((int)(f & 1023)) << 2;
    float4 v = *reinterpret_cast<const float4*>(x + f * 4);

    int mb = m >> 7, mr = m & 127;
    int warp_m = mr >> 6, mf = (mr >> 4) & 3, half_m = (mr >> 3) & 1, gid = mr & 7;
    int kb = k >> 6, kc = k & 63;
    int ks = kc >> 4, kk = kc & 15;
    int tig = (kk >> 1) & 3, khi = kk >> 3;   // kk in {0,4,8,12}: klo=0
    int e0 = 2 * half_m + 4 * khi;

    __half* tile = g_xt + (size_t)(mb * KBLKS + kb) * TILE_H;
    int off = (((warp_m * 4 + mf) * 4 + ks) * 32 + gid * 4 + tig) * 8 + e0;
    *reinterpret_cast<__half2*>(tile + off)     = __floats2half2_rn(v.x, v.y);
    *reinterpret_cast<__half2*>(tile + off + 8) = __floats2half2_rn(v.z, v.w);  // tig+1
}

// ============================================================================
// Pre-pass 2: Wc[n][h] = W[n][h] + SCALING * sum_r A[h][r]*B[r][n] -> fp16(RNE),
// fragment-packed B tiles. (n,k=h): warp_n=nr>>5, nf=(nr>>3)&3 -> pair=nf>>1,
// odd=nf&1, gid=nr&7.  e = klo + 2*khi + 4*odd.
// ============================================================================
__global__ __launch_bounds__(256) void prep_w(
    const float* __restrict__ Wq, const float* __restrict__ Wk, const float* __restrict__ Wv,
    const float* __restrict__ Aq, const float* __restrict__ Bq,
    const float* __restrict__ Ak, const float* __restrict__ Bk,
    const float* __restrict__ Av, const float* __restrict__ Bv) {
    __shared__ float sB[16][16];   // [r][j] = B[r][n0+j]
    const int h  = blockIdx.x * 256 + threadIdx.x;
    const int n0 = blockIdx.y * 16;

    const float *W, *A, *Bm;
    int nn0, od;
    if (n0 < NQ)            { W = Wq; A = Aq; Bm = Bq; nn0 = n0;             od = NQ;  }
    else if (n0 < NQ + NKV) { W = Wk; A = Ak; Bm = Bk; nn0 = n0 - NQ;        od = NKV; }
    else                    { W = Wv; A = Av; Bm = Bv; nn0 = n0 - NQ - NKV;  od = NKV; }

    {
        int r = threadIdx.x >> 4, j = threadIdx.x & 15;
        sB[r][j] = Bm[r * od + nn0 + j];
    }
    __syncthreads();

    float a[16];
    const float4* ap = reinterpret_cast<const float4*>(A + (size_t)h * 16);
    #pragma unroll
    for (int q = 0; q < 4; q++) {
        float4 v = ap[q];
        a[q * 4 + 0] = v.x; a[q * 4 + 1] = v.y; a[q * 4 + 2] = v.z; a[q * 4 + 3] = v.w;
    }

    // k-decomposition for this h (shared by all 16 n)
    int kb = h >> 6, kc = h & 63;
    int ks = kc >> 4, kk = kc & 15;
    int tig = (kk >> 1) & 3, klo = kk & 1, khi = kk >> 3;

    #pragma unroll
    for (int j = 0; j < 16; j++) {
        float acc = W[(size_t)(nn0 + j) * KTOT + h];
        #pragma unroll
        for (int r = 0; r < 16; r++)
            acc += SCALING * a[r] * sB[r][j];
        int n = n0 + j;
        int nb = n >> 7, nr = n & 127;
        int warp_n = nr >> 5, nf = (nr >> 3) & 3, gid = nr & 7;
        int pair = nf >> 1, odd = nf & 1;
        __half* tile = g_wc + (size_t)(nb * KBLKS + kb) * TILE_H;
        int off = (((warp_n * 2 + pair) * 4 + ks) * 32 + gid * 4 + tig) * 8
                + klo + 2 * khi + 4 * odd;
        tile[off] = __float2half_rn(acc);
    }
}

__global__ __launch_bounds__(256) void prep_bias(const float* __restrict__ bq,
                                                 const float* __restrict__ bk,
                                                 const float* __restrict__ bv) {
    int n = blockIdx.x * 256 + threadIdx.x;
    if (n >= NTOT) return;
    g_bias[n] = (n < NQ) ? bq[n] : (n < NQ + NKV ? bk[n - NQ] : bv[n - NQ - NKV]);
}

// ============================================================================
// Main GEMM: 128x128x64 CTA, 8 warps (64x32 warp tiles), 3-stage cp.async,
// fragment-packed smem -> pure LDS.128, mma.sync m16n8k16 fp16.
// One __syncthreads per K-iteration.
// ============================================================================
__global__ __launch_bounds__(256, 2) void gemm_kernel(float* __restrict__ out) {
    extern __shared__ char smem[];   // [STAGES][A tile | B tile]
    const int tid = threadIdx.x, wid = tid >> 5, lane = tid & 31;
    const int gid = lane >> 2, tig = lane & 3;
    const int warp_m = wid & 1, warp_n = wid >> 1;

    constexpr int GROUP_M = 16;
    constexpr int GS = GROUP_M * NBLKS;
    int gi = blockIdx.x / GS, rem = blockIdx.x - gi * GS;
    int pm = gi * GROUP_M + (rem % GROUP_M);
    int pn = rem / GROUP_M;

    const __half* abase = g_xt + (size_t)pm * KBLKS * TILE_H;
    const __half* bbase = g_wc + (size_t)pn * KBLKS * TILE_H;
    uint32_t sb = smem_u32(smem);

    // contiguous tile copy: 1024 float4 per matrix, 4 per thread each
    auto load_stage = [&](int kb, int st) {
        const char* as = reinterpret_cast<const char*>(abase + (size_t)kb * TILE_H);
        const char* bs = reinterpret_cast<const char*>(bbase + (size_t)kb * TILE_H);
        uint32_t dA = sb + (uint32_t)(st * 2 * TILE_BYTES);
        uint32_t dB = dA + TILE_BYTES;
        #pragma unroll
        for (int i = 0; i < 4; i++) {
            int byte = (tid + i * 256) * 16;
            CP_ASYNC16(dA + byte, as + byte);
            CP_ASYNC16(dB + byte, bs + byte);
        }
        CP_COMMIT();
    };

    #pragma unroll
    for (int s = 0; s < STAGES - 1; s++) load_stage(s, s);

    float acc[4][4][4];
    #pragma unroll
    for (int i = 0; i < 4; i++)
        #pragma unroll
        for (int j = 0; j < 4; j++)
            #pragma unroll
            for (int k = 0; k < 4; k++) acc[i][j][k] = 0.0f;

    // per-warp fragment byte offsets
    // A frag: ((warp_m*16 + mf*4 + ks)*32 + lane) * 16 bytes
    // B frag: TILE_BYTES + ((warp_n*8 + pair*4 + ks)*32 + lane) * 16 bytes
    const int aoff0 = (warp_m * 16 * 32 + lane) * 16;
    const int boff0 = TILE_BYTES + (warp_n * 8 * 32 + lane) * 16;

    int st = 0;
    for (int kb = 0; kb < KBLKS; kb++) {
        CP_WAIT(STAGES - 2);
        __syncthreads();   // also orders last iter's reads before overwrite below

        int nkb = kb + STAGES - 1;
        if (nkb < KBLKS) load_stage(nkb, (st + STAGES - 1) % STAGES);
        else CP_COMMIT();

        const char* sbase = smem + st * 2 * TILE_BYTES;

        #pragma unroll
        for (int ks = 0; ks < 4; ks++) {
            uint4 a[4], bq[2];
            #pragma unroll
            for (int mf = 0; mf < 4; mf++)
                a[mf] = *reinterpret_cast<const uint4*>(sbase + aoff0 + (mf * 4 + ks) * 512);
            #pragma unroll
            for (int p = 0; p < 2; p++)
                bq[p] = *reinterpret_cast<const uint4*>(sbase + boff0 + (p * 4 + ks) * 512);
            #pragma unroll
            for (int mf = 0; mf < 4; mf++) {
                mma_f16(acc[mf][0], a[mf], bq[0].x, bq[0].y);
                mma_f16(acc[mf][1], a[mf], bq[0].z, bq[0].w);
                mma_f16(acc[mf][2], a[mf], bq[1].x, bq[1].y);
                mma_f16(acc[mf][3], a[mf], bq[1].z, bq[1].w);
            }
        }
        st = (st + 1) % STAGES;
    }

    // ---- epilogue: bias + store ----
    const int n_tile0 = pn * BN;
    float* obase;
    int ncols;
    if (n_tile0 < NQ)            { obase = out;                             ncols = NQ;  }
    else if (n_tile0 < NQ + NKV) { obase = out + (size_t)MTOT * NQ;         ncols = NKV; }
    else                         { obase = out + (size_t)MTOT * (NQ + NKV); ncols = NKV; }
    int nseg0 = (n_tile0 < NQ) ? n_tile0 : (n_tile0 < NQ + NKV ? n_tile0 - NQ : n_tile0 - NQ - NKV);

    #pragma unroll
    for (int mf = 0; mf < 4; mf++) {
        int m0 = pm * BM + warp_m * 64 + mf * 16 + gid;
        #pragma unroll
        for (int nf = 0; nf < 4; nf++) {
            int nc = warp_n * 32 + nf * 8 + tig * 2;
            int ng = n_tile0 + nc;
            float b0 = g_bias[ng], b1 = g_bias[ng + 1];
            float2 v0 = make_float2(acc[mf][nf][0] + b0, acc[mf][nf][1] + b1);
            float2 v1 = make_float2(acc[mf][nf][2] + b0, acc[mf][nf][3] + b1);
            *reinterpret_cast<float2*>(obase + (size_t)m0 * ncols + nseg0 + nc)       = v0;
            *reinterpret_cast<float2*>(obase + (size_t)(m0 + 8) * ncols + nseg0 + nc) = v1;
        }
    }
}

// ============================================================================
// kernel_launch
// ============================================================================
extern "C" void kernel_launch(void* const* d_in, const int* in_sizes, int n_in,
                              void* d_out, int out_size) {
    const float* x  = (const float*)d_in[0];
    const float* Wq = (const float*)d_in[1];
    const float* Wk = (const float*)d_in[2];
    const float* Wv = (const float*)d_in[3];
    const float* bq = (const float*)d_in[4];
    const float* bk = (const float*)d_in[5];
    const float* bv = (const float*)d_in[6];
    const float* Aq = (const float*)d_in[7];
    const float* Bq = (const float*)d_in[8];
    const float* Ak = (const float*)d_in[9];
    const float* Bk = (const float*)d_in[10];
    const float* Av = (const float*)d_in[11];
    const float* Bv = (const float*)d_in[12];
    float* out = (float*)d_out;

    cudaFuncSetAttribute(gemm_kernel, cudaFuncAttributeMaxDynamicSharedMemorySize, SMEM_TOTAL);

    prep_x<<<(int)(((size_t)MTOT * KTOT / 4) / 256), 256>>>(x);
    {
        dim3 g(KTOT / 256, NTOT / 16);
        prep_w<<<g, 256>>>(Wq, Wk, Wv, Aq, Bq, Ak, Bk, Av, Bv);
    }
    prep_bias<<<(NTOT + 255) / 256, 256>>>(bq, bk, bv);
    gemm_kernel<<<MBLKS * NBLKS, 256, SMEM_TOTAL>>>(out);
}